// round 3
// baseline (speedup 1.0000x reference)
#include <cuda_runtime.h>
#include <math.h>

#define Dm      128
#define BATCH   65536
#define NROWS   500000
#define TSLOTS  3
#define SWW     132

#define AS_FLOATS   (128 * 128)
#define SMEM_FLOATS (AS_FLOATS * 2 + 128 * SWW)
#define SMEM_BYTES  (SMEM_FLOATS * 4)

__device__ int g_winner[NROWS];

// ---------------- helpers ----------------

// transposed activation layout: element (feature k, row r) at k*128 + (r XOR-swizzled)
__device__ __forceinline__ int aoff(int k, int r) {
    return k * 128 + (r ^ (((k >> 3) & 15) << 3));
}

__device__ __forceinline__ unsigned long long pk2(float v) {
    unsigned long long r;
    asm("mov.b64 %0, {%1, %1};" : "=l"(r) : "f"(v));
    return r;
}
__device__ __forceinline__ void ffma2(unsigned long long& d,
                                      unsigned long long a,
                                      unsigned long long b) {
    asm("fma.rn.f32x2 %0, %1, %2, %0;" : "+l"(d) : "l"(a), "l"(b));
}
__device__ __forceinline__ float2 upk(unsigned long long v) {
    float2 f;
    asm("mov.b64 {%0, %1}, %2;" : "=f"(f.x), "=f"(f.y) : "l"(v));
    return f;
}
__device__ __forceinline__ float sigf(float x) { return 1.0f / (1.0f + expf(-x)); }

// stage W tile: Ws[k][c] = Wg[c*128 + k]   (Wg row-major [out_c][in_k])
__device__ __forceinline__ void stage_W(float* __restrict__ Ws,
                                        const float* __restrict__ Wg, int tid) {
    const float4* W4 = (const float4*)Wg;
#pragma unroll
    for (int m = 0; m < 16; m++) {
        int f4 = tid + m * 256;      // float4 index over 4096
        int c  = f4 >> 5;            // 32 float4 per row of 128
        int kq = f4 & 31;
        float4 v = W4[f4];           // == Wg[c][4*kq .. 4*kq+3], coalesced
        int kk = kq * 4;
        Ws[(kk + 0) * SWW + c] = v.x;
        Ws[(kk + 1) * SWW + c] = v.y;
        Ws[(kk + 2) * SWW + c] = v.z;
        Ws[(kk + 3) * SWW + c] = v.w;
    }
}

// acc[r_i][c_pair] += A^T[k][r0+i] * Ws[k][c0+j]; acc packed as f32x2 col pairs
__device__ __forceinline__ void gemm_acc(const float* __restrict__ A,
                                         const float* __restrict__ Ws,
                                         unsigned long long acc[32],
                                         int r0, int c0) {
#pragma unroll 4
    for (int k = 0; k < 128; k++) {
        int sw = ((k >> 3) & 15) << 3;
        const float* abase = A + k * 128 + (r0 ^ sw);
        float4 a0 = *(const float4*)(abase);
        float4 a1 = *(const float4*)(abase + 4);
        const ulonglong2* wrow = (const ulonglong2*)(Ws + k * SWW + c0);
        ulonglong2 w01 = wrow[0];   // .x = cols(c0,c0+1) .y = cols(c0+2,c0+3)
        ulonglong2 w23 = wrow[1];
        unsigned long long ap[8];
        ap[0] = pk2(a0.x); ap[1] = pk2(a0.y); ap[2] = pk2(a0.z); ap[3] = pk2(a0.w);
        ap[4] = pk2(a1.x); ap[5] = pk2(a1.y); ap[6] = pk2(a1.z); ap[7] = pk2(a1.w);
#pragma unroll
        for (int i = 0; i < 8; i++) {
            ffma2(acc[i * 4 + 0], ap[i], w01.x);
            ffma2(acc[i * 4 + 1], ap[i], w01.y);
            ffma2(acc[i * 4 + 2], ap[i], w23.x);
            ffma2(acc[i * 4 + 3], ap[i], w23.y);
        }
    }
}

#define ZERO_ACC                                            \
    _Pragma("unroll") for (int zz = 0; zz < 32; zz++) acc[zz] = 0ULL;

// ---------------- winner kernels ----------------

__global__ void k_winit() {
    int i = blockIdx.x * blockDim.x + threadIdx.x;
    if (i < NROWS) g_winner[i] = -1;
}

__global__ void k_wscatter(const int* __restrict__ idx) {
    int b = blockIdx.x * blockDim.x + threadIdx.x;
    if (b < BATCH) atomicMax(&g_winner[idx[b]], b);
}

// ---------------- fused compute kernel ----------------
// per 128-row tile: h1=elu(x@W1^T+b1); xf=h1@W2^T+b2; mem=hist[2][idx];
// GRU gates via 6 more GEMMs; out=(1-z)*n + z*mem; writes out + mem.

__global__ void __launch_bounds__(256, 1) k_compute(
    const float* __restrict__ x, const int* __restrict__ idx,
    const float* __restrict__ hist,
    const float* __restrict__ W1, const float* __restrict__ b1,
    const float* __restrict__ W2, const float* __restrict__ b2,
    const float* __restrict__ W_ih, const float* __restrict__ b_ih,
    const float* __restrict__ W_hh, const float* __restrict__ b_hh,
    float* __restrict__ out, float* __restrict__ memout)
{
    extern __shared__ float sm[];
    float* As = sm;                  // xf / activations, transposed [k][r]
    float* Ms = sm + AS_FLOATS;      // mem, transposed [k][r]
    float* Ws = sm + 2 * AS_FLOATS;  // weight tile [k][c], stride SWW

    const int tid = threadIdx.x;
    const int tx  = tid & 15;
    const int ty  = tid >> 4;
    const int r0  = ty * 8;
    const int c0  = tx * 8;
    const long long rowbase = (long long)blockIdx.x * 128;

    // ---- load x tile and gather mem tile (transposed into smem), write mem out ----
    {
        int row  = tid >> 1;
        int half = tid & 1;
        const float4* xr = (const float4*)(x + (rowbase + row) * Dm) + half * 16;
        long long gi = (long long)idx[rowbase + row];
        const float4* mr =
            (const float4*)(hist + ((long long)(TSLOTS - 1) * NROWS + gi) * Dm) + half * 16;
        float4* mo = (float4*)(memout + (rowbase + row) * Dm) + half * 16;
#pragma unroll
        for (int m = 0; m < 16; m++) {
            float4 vx = xr[m];
            float4 vm = mr[m];
            mo[m] = vm;
            int k = half * 64 + m * 4;
            As[aoff(k + 0, row)] = vx.x;
            As[aoff(k + 1, row)] = vx.y;
            As[aoff(k + 2, row)] = vx.z;
            As[aoff(k + 3, row)] = vx.w;
            Ms[aoff(k + 0, row)] = vm.x;
            Ms[aoff(k + 1, row)] = vm.y;
            Ms[aoff(k + 2, row)] = vm.z;
            Ms[aoff(k + 3, row)] = vm.w;
        }
    }

    unsigned long long acc[32];
    float hold[8][8];   // r -> r*ghn -> n
    float v[8][8];      // scratch

    // ===== GEMM 1: h1 = elu(x@W1^T + b1) =====
    stage_W(Ws, W1, tid);
    __syncthreads();
    ZERO_ACC;
    gemm_acc(As, Ws, acc, r0, c0);
    __syncthreads();   // all reads of As/Ws done
    {
        float bb[8];
#pragma unroll
        for (int j = 0; j < 8; j++) bb[j] = b1[c0 + j];
#pragma unroll
        for (int i = 0; i < 8; i++)
#pragma unroll
            for (int j2 = 0; j2 < 4; j2++) {
                float2 p = upk(acc[i * 4 + j2]);
                float a = p.x + bb[2 * j2];
                float b = p.y + bb[2 * j2 + 1];
                v[i][2 * j2]     = (a > 0.f) ? a : expm1f(a);
                v[i][2 * j2 + 1] = (b > 0.f) ? b : expm1f(b);
            }
        // write h1^T back into As
#pragma unroll
        for (int j = 0; j < 8; j++) {
            int c = c0 + j;
            float* base = As + c * 128 + (r0 ^ (((c >> 3) & 15) << 3));
            *(float4*)(base)     = make_float4(v[0][j], v[1][j], v[2][j], v[3][j]);
            *(float4*)(base + 4) = make_float4(v[4][j], v[5][j], v[6][j], v[7][j]);
        }
    }
    stage_W(Ws, W2, tid);
    __syncthreads();

    // ===== GEMM 2: xf = h1@W2^T + b2 =====
    ZERO_ACC;
    gemm_acc(As, Ws, acc, r0, c0);
    __syncthreads();
    {
        float bb[8];
#pragma unroll
        for (int j = 0; j < 8; j++) bb[j] = b2[c0 + j];
#pragma unroll
        for (int i = 0; i < 8; i++)
#pragma unroll
            for (int j2 = 0; j2 < 4; j2++) {
                float2 p = upk(acc[i * 4 + j2]);
                v[i][2 * j2]     = p.x + bb[2 * j2];
                v[i][2 * j2 + 1] = p.y + bb[2 * j2 + 1];
            }
#pragma unroll
        for (int j = 0; j < 8; j++) {
            int c = c0 + j;
            float* base = As + c * 128 + (r0 ^ (((c >> 3) & 15) << 3));
            *(float4*)(base)     = make_float4(v[0][j], v[1][j], v[2][j], v[3][j]);
            *(float4*)(base + 4) = make_float4(v[4][j], v[5][j], v[6][j], v[7][j]);
        }
    }

    // ===== r gate: r = sigmoid(xf@Wihr^T + mem@Whhr^T + b_ihr + b_hhr) =====
    stage_W(Ws, W_ih, tid);
    __syncthreads();
    ZERO_ACC;
    gemm_acc(As, Ws, acc, r0, c0);
    __syncthreads();
    stage_W(Ws, W_hh, tid);
    __syncthreads();
    gemm_acc(Ms, Ws, acc, r0, c0);
    {
        float ba[8], bb[8];
#pragma unroll
        for (int j = 0; j < 8; j++) { ba[j] = b_ih[c0 + j]; bb[j] = b_hh[c0 + j]; }
#pragma unroll
        for (int i = 0; i < 8; i++)
#pragma unroll
            for (int j2 = 0; j2 < 4; j2++) {
                float2 p = upk(acc[i * 4 + j2]);
                hold[i][2 * j2]     = sigf(p.x + ba[2 * j2] + bb[2 * j2]);
                hold[i][2 * j2 + 1] = sigf(p.y + ba[2 * j2 + 1] + bb[2 * j2 + 1]);
            }
    }
    __syncthreads();

    // ===== ghn: hold = r * (mem@Whhn^T + b_hhn) =====
    stage_W(Ws, W_hh + 2 * 16384, tid);
    __syncthreads();
    ZERO_ACC;
    gemm_acc(Ms, Ws, acc, r0, c0);
    {
        float bb[8];
#pragma unroll
        for (int j = 0; j < 8; j++) bb[j] = b_hh[256 + c0 + j];
#pragma unroll
        for (int i = 0; i < 8; i++)
#pragma unroll
            for (int j2 = 0; j2 < 4; j2++) {
                float2 p = upk(acc[i * 4 + j2]);
                hold[i][2 * j2]     *= (p.x + bb[2 * j2]);
                hold[i][2 * j2 + 1] *= (p.y + bb[2 * j2 + 1]);
            }
    }
    __syncthreads();

    // ===== i_n: hold = tanh(xf@Wihn^T + b_ihn + hold) =====
    stage_W(Ws, W_ih + 2 * 16384, tid);
    __syncthreads();
    ZERO_ACC;
    gemm_acc(As, Ws, acc, r0, c0);
    {
        float bb[8];
#pragma unroll
        for (int j = 0; j < 8; j++) bb[j] = b_ih[256 + c0 + j];
#pragma unroll
        for (int i = 0; i < 8; i++)
#pragma unroll
            for (int j2 = 0; j2 < 4; j2++) {
                float2 p = upk(acc[i * 4 + j2]);
                hold[i][2 * j2]     = tanhf(p.x + bb[2 * j2] + hold[i][2 * j2]);
                hold[i][2 * j2 + 1] = tanhf(p.y + bb[2 * j2 + 1] + hold[i][2 * j2 + 1]);
            }
    }
    __syncthreads();

    // ===== z gate + combine =====
    stage_W(Ws, W_ih + 16384, tid);
    __syncthreads();
    ZERO_ACC;
    gemm_acc(As, Ws, acc, r0, c0);
    __syncthreads();
    stage_W(Ws, W_hh + 16384, tid);
    __syncthreads();
    gemm_acc(Ms, Ws, acc, r0, c0);
    {
        float ba[8], bb[8];
#pragma unroll
        for (int j = 0; j < 8; j++) { ba[j] = b_ih[128 + c0 + j]; bb[j] = b_hh[128 + c0 + j]; }
        // mem values for this thread's patch from Ms
        float mv[8][8];
#pragma unroll
        for (int j = 0; j < 8; j++) {
            int c = c0 + j;
            const float* base = Ms + c * 128 + (r0 ^ (((c >> 3) & 15) << 3));
            float4 lo = *(const float4*)(base);
            float4 hi = *(const float4*)(base + 4);
            mv[0][j] = lo.x; mv[1][j] = lo.y; mv[2][j] = lo.z; mv[3][j] = lo.w;
            mv[4][j] = hi.x; mv[5][j] = hi.y; mv[6][j] = hi.z; mv[7][j] = hi.w;
        }
#pragma unroll
        for (int i = 0; i < 8; i++) {
            float o[8];
#pragma unroll
            for (int j2 = 0; j2 < 4; j2++) {
                float2 p = upk(acc[i * 4 + j2]);
                float z0 = sigf(p.x + ba[2 * j2] + bb[2 * j2]);
                float z1 = sigf(p.y + ba[2 * j2 + 1] + bb[2 * j2 + 1]);
                o[2 * j2]     = (1.f - z0) * hold[i][2 * j2]     + z0 * mv[i][2 * j2];
                o[2 * j2 + 1] = (1.f - z1) * hold[i][2 * j2 + 1] + z1 * mv[i][2 * j2 + 1];
            }
            float* orow = out + (rowbase + r0 + i) * Dm + c0;
            *(float4*)(orow)     = make_float4(o[0], o[1], o[2], o[3]);
            *(float4*)(orow + 4) = make_float4(o[4], o[5], o[6], o[7]);
        }
    }
}

// ---------------- fused history shift/scatter ----------------

__global__ void k_hist(const float* __restrict__ hist,
                       const float* __restrict__ out,
                       float* __restrict__ nh)
{
    const long long PER_T = (long long)NROWS * (Dm / 4);
    int t = blockIdx.y;
    long long rem = (long long)blockIdx.x * blockDim.x + threadIdx.x;  // over N*D/4
    int i  = (int)(rem >> 5);     // D/4 = 32 float4 per row
    int c4 = (int)(rem & 31);
    int w = g_winner[i];
    long long gid = (long long)t * PER_T + rem;
    float4 val;
    if (w < 0) {
        val = ((const float4*)hist)[gid];
    } else if (t < TSLOTS - 1) {
        val = ((const float4*)hist)[gid + PER_T];
    } else {
        val = ((const float4*)out)[(long long)w * (Dm / 4) + c4];
    }
    ((float4*)nh)[gid] = val;
}

// ---------------- launcher ----------------

extern "C" void kernel_launch(void* const* d_in, const int* in_sizes, int n_in,
                              void* d_out, int out_size) {
    (void)in_sizes; (void)n_in; (void)out_size;
    const float* x    = (const float*)d_in[0];
    const int*   idx  = (const int*)d_in[1];
    const float* hist = (const float*)d_in[2];
    const float* W1   = (const float*)d_in[3];
    const float* b1   = (const float*)d_in[4];
    const float* W2   = (const float*)d_in[5];
    const float* b2   = (const float*)d_in[6];
    const float* W_ih = (const float*)d_in[7];
    const float* b_ih = (const float*)d_in[8];
    const float* W_hh = (const float*)d_in[9];
    const float* b_hh = (const float*)d_in[10];

    float* out    = (float*)d_out;
    float* memout = out + (long long)BATCH * Dm;
    float* nh     = memout + (long long)BATCH * Dm;

    cudaFuncSetAttribute(k_compute, cudaFuncAttributeMaxDynamicSharedMemorySize, SMEM_BYTES);

    k_winit<<<(NROWS + 511) / 512, 512>>>();
    k_wscatter<<<(BATCH + 255) / 256, 256>>>(idx);
    k_compute<<<BATCH / 128, 256, SMEM_BYTES>>>(x, idx, hist, W1, b1, W2, b2,
                                                W_ih, b_ih, W_hh, b_hh, out, memout);
    dim3 hg((unsigned)((long long)NROWS * (Dm / 4) / 256), TSLOTS);
    k_hist<<<hg, 256>>>(hist, out, nh);
}